// round 5
// baseline (speedup 1.0000x reference)
#include <cuda_runtime.h>
#include <cuda_bf16.h>
#include <cstdint>

#define NB 65536   // batch
#define ND 512     // embed dim
#define NP 1024    // prototypes
#define MARGIN 0.08f
#define CAP 16

// Device-global scratch (no runtime allocation allowed)
static __device__ float          g_cnorm[NP * ND];      // normalized centroids fp32
static __device__ __nv_bfloat16  g_cnorm_bf[NP * ND];   // normalized centroids bf16

// Order-preserving float<->uint mapping (for atomicMax on floats)
__device__ __forceinline__ unsigned fmap(float f) {
    unsigned u = __float_as_uint(f);
    return (u & 0x80000000u) ? ~u : (u | 0x80000000u);
}
__device__ __forceinline__ float funmap(unsigned u) {
    u = (u & 0x80000000u) ? (u & 0x7fffffffu) : ~u;
    return __uint_as_float(u);
}

__device__ __forceinline__ uint32_t smem_u32(const void* p) {
    uint32_t a;
    asm("{ .reg .u64 t; cvta.to.shared.u64 t, %1; cvt.u32.u64 %0, t; }"
        : "=r"(a) : "l"(p));
    return a;
}

__device__ __forceinline__ void ldsm_x4(unsigned& r0, unsigned& r1,
                                        unsigned& r2, unsigned& r3, uint32_t addr) {
    asm volatile("ldmatrix.sync.aligned.m8n8.x4.shared.b16 {%0,%1,%2,%3}, [%4];"
                 : "=r"(r0), "=r"(r1), "=r"(r2), "=r"(r3) : "r"(addr));
}

__device__ __forceinline__ void mma16816(float* c, const unsigned* a, const unsigned* b) {
    asm volatile(
        "mma.sync.aligned.m16n8k16.row.col.f32.bf16.bf16.f32 "
        "{%0,%1,%2,%3},{%4,%5,%6,%7},{%8,%9},{%0,%1,%2,%3};\n"
        : "+f"(c[0]), "+f"(c[1]), "+f"(c[2]), "+f"(c[3])
        : "r"(a[0]), "r"(a[1]), "r"(a[2]), "r"(a[3]), "r"(b[0]), "r"(b[1]));
}

// ---------------------------------------------------------------------------
// Kernel 1: L2-normalize centroids -> fp32 + bf16 copies.
// ---------------------------------------------------------------------------
__global__ void normalize_centroids(const float* __restrict__ cent) {
    int row = blockIdx.x;
    int t   = threadIdx.x;  // 0..127
    float4 v = reinterpret_cast<const float4*>(cent + (size_t)row * ND)[t];
    float ss = v.x * v.x + v.y * v.y + v.z * v.z + v.w * v.w;
    #pragma unroll
    for (int o = 16; o > 0; o >>= 1) ss += __shfl_down_sync(0xffffffffu, ss, o);
    __shared__ float sred[4];
    if ((t & 31) == 0) sred[t >> 5] = ss;
    __syncthreads();
    float tot   = sred[0] + sred[1] + sred[2] + sred[3];
    float scale = 1.0f / fmaxf(sqrtf(tot), 1e-12f);
    float4 o4 = make_float4(v.x * scale, v.y * scale, v.z * scale, v.w * scale);
    reinterpret_cast<float4*>(g_cnorm + (size_t)row * ND)[t] = o4;
    __nv_bfloat162 p0 = __floats2bfloat162_rn(o4.x, o4.y);
    __nv_bfloat162 p1 = __floats2bfloat162_rn(o4.z, o4.w);
    uint2 pk = make_uint2(*reinterpret_cast<unsigned*>(&p0),
                          *reinterpret_cast<unsigned*>(&p1));
    reinterpret_cast<uint2*>(g_cnorm_bf)[(size_t)row * (ND / 4) + t] = pk;
}

// ---------------------------------------------------------------------------
// Kernel 2: fused GEMM-argmax. 256 threads (8 warps), CTA owns 128 rows.
//  - A resident in smem bf16 (128 x 512, stride 520)
//  - B streamed via cp.async.cg, 4-deep ring of 128x64 chunks (stride 72)
//  - ldmatrix fragment loads, mma.sync bf16 HMMA
//  - per-n-tile running max + margin candidates, exact fp32 refinement,
//    fused output writes (context gather, hard index, full one-hot)
// ---------------------------------------------------------------------------
#define ASTR 520        // bf16 elems per A row (512 + 8 pad -> 1040B, 65x16B)
#define BSTR 72         // bf16 elems per B row (64 + 8 pad -> 144B, 9x16B)
#define OFF_STATM 0                      // rowMaxU: 128 u32
#define OFF_CNT   512                    // rowCnt:  128 int
#define OFF_CAND  1024                   // cand:    128*CAP ushort (4096B)
#define OFF_A     5120
#define OFF_B     (OFF_A + 128 * ASTR * 2)   // 138240
#define BUFB      (128 * BSTR * 2)           // 18432
#define SMEM_TOTAL (OFF_B + 4 * BUFB)        // 211968

__global__ __launch_bounds__(256, 1) void fused_kernel(
    const float* __restrict__ q, const float* __restrict__ cent,
    float* __restrict__ out) {
    extern __shared__ char sm[];
    uint32_t sb = smem_u32(sm);
    unsigned*       rowMaxU = reinterpret_cast<unsigned*>(sm + OFF_STATM);
    int*            rowCnt  = reinterpret_cast<int*>(sm + OFF_CNT);
    unsigned short* cand    = reinterpret_cast<unsigned short*>(sm + OFF_CAND);
    __nv_bfloat16*  sA      = reinterpret_cast<__nv_bfloat16*>(sm + OFF_A);

    const unsigned FULL = 0xffffffffu;
    int tid  = threadIdx.x;
    int lane = tid & 31, wid = tid >> 5;
    int warpM = wid & 1, warpN = wid >> 1;   // 2 x 4 warp grid, warp tile 64x32
    int g = lane >> 2, tc = lane & 3;
    int m0 = blockIdx.x * 128;

    if (tid < 128) { rowMaxU[tid] = 0u; rowCnt[tid] = 0; }

    // ---- Load resident A tile: 128 x 512 fp32 -> bf16 ----
    const float4* q4 = reinterpret_cast<const float4*>(q);
    #pragma unroll 4
    for (int e = tid; e < 128 * 128; e += 256) {
        int row = e >> 7, c = e & 127;
        float4 v = q4[(size_t)(m0 + row) * 128 + c];
        __nv_bfloat162 p0 = __floats2bfloat162_rn(v.x, v.y);
        __nv_bfloat162 p1 = __floats2bfloat162_rn(v.z, v.w);
        uint2 pk = make_uint2(*reinterpret_cast<unsigned*>(&p0),
                              *reinterpret_cast<unsigned*>(&p1));
        *reinterpret_cast<uint2*>(&sA[row * ASTR + c * 4]) = pk;
    }

    float acc[4][4][4];
    #pragma unroll
    for (int mt = 0; mt < 4; mt++)
        #pragma unroll
        for (int nt = 0; nt < 4; nt++)
            #pragma unroll
            for (int i = 0; i < 4; i++) acc[mt][nt][i] = 0.0f;

    // B streaming: chunk c = (n-tile c>>3) x (k-chunk c&7), 128 rows x 64 k.
    // Each thread loads half a row (64B) per chunk via 4x cp.async 16B.
    int brow_ld = tid >> 1, bhalf = tid & 1;
    uint32_t dst_base = sb + OFF_B + brow_ld * 144 + bhalf * 64;
    const char* src_base = reinterpret_cast<const char*>(g_cnorm_bf) +
                           (size_t)brow_ld * 1024 + bhalf * 64;
    auto issue_chunk = [&](int c) {
        uint32_t dst = dst_base + (c & 3) * BUFB;
        const char* src = src_base + (size_t)(c >> 3) * 131072 + (c & 7) * 128;
        #pragma unroll
        for (int i = 0; i < 4; i++)
            asm volatile("cp.async.cg.shared.global [%0], [%1], 16;"
                         :: "r"(dst + i * 16), "l"(src + i * 16));
        asm volatile("cp.async.commit_group;" ::: "memory");
    };
    issue_chunk(0); issue_chunk(1); issue_chunk(2);

    // ldmatrix per-lane address components
    uint32_t aAddr = sb + OFF_A +
        ((warpM * 64 + (lane & 15)) * ASTR + ((lane >> 4) << 3)) * 2;
    uint32_t bOff =
        ((warpN * 32 + (lane & 7) + ((lane >> 4) << 3)) * BSTR +
         (((lane >> 3) & 1) << 3)) * 2;

    // ---- Main loop: 64 chunks = 8 n-tiles x 8 k-steps of 64 ----
    for (int c = 0; c < 64; c++) {
        if (c <= 61)      asm volatile("cp.async.wait_group 2;" ::: "memory");
        else if (c == 62) asm volatile("cp.async.wait_group 1;" ::: "memory");
        else              asm volatile("cp.async.wait_group 0;" ::: "memory");
        __syncthreads();
        if (c + 3 < 64) issue_chunk(c + 3);

        uint32_t bufbase = sb + OFF_B + (c & 3) * BUFB + bOff;
        int kbase = (c & 7) * 64;

        #pragma unroll
        for (int kk = 0; kk < 64; kk += 16) {
            unsigned a[4][4], b[4][2];
            #pragma unroll
            for (int mt = 0; mt < 4; mt++)
                ldsm_x4(a[mt][0], a[mt][1], a[mt][2], a[mt][3],
                        aAddr + (mt * 16 * ASTR + kbase + kk) * 2);
            #pragma unroll
            for (int p = 0; p < 2; p++) {
                unsigned r0, r1, r2, r3;
                ldsm_x4(r0, r1, r2, r3, bufbase + (p * 16 * BSTR + kk) * 2);
                b[2 * p][0] = r0; b[2 * p][1] = r1;
                b[2 * p + 1][0] = r2; b[2 * p + 1][1] = r3;
            }
            #pragma unroll
            for (int mt = 0; mt < 4; mt++)
                #pragma unroll
                for (int nt = 0; nt < 4; nt++)
                    mma16816(acc[mt][nt], a[mt], b[nt]);
        }

        if ((c & 7) == 7) {   // n-tile finished: argmax epilogue
            int n0 = (c >> 3) * 128;
            #pragma unroll
            for (int mt = 0; mt < 4; mt++) {
                float v0 = -3.4e38f, v1 = -3.4e38f;
                #pragma unroll
                for (int nt = 0; nt < 4; nt++) {
                    v0 = fmaxf(v0, fmaxf(acc[mt][nt][0], acc[mt][nt][1]));
                    v1 = fmaxf(v1, fmaxf(acc[mt][nt][2], acc[mt][nt][3]));
                }
                v0 = fmaxf(v0, __shfl_xor_sync(FULL, v0, 1));
                v0 = fmaxf(v0, __shfl_xor_sync(FULL, v0, 2));
                v1 = fmaxf(v1, __shfl_xor_sync(FULL, v1, 1));
                v1 = fmaxf(v1, __shfl_xor_sync(FULL, v1, 2));
                if (tc == 0) {
                    int r = warpM * 64 + mt * 16 + g;
                    atomicMax(&rowMaxU[r], fmap(v0));
                    atomicMax(&rowMaxU[r + 8], fmap(v1));
                }
            }
            __syncthreads();
            #pragma unroll
            for (int mt = 0; mt < 4; mt++) {
                int r0 = warpM * 64 + mt * 16 + g;
                float th0 = funmap(rowMaxU[r0]) - MARGIN;
                float th1 = funmap(rowMaxU[r0 + 8]) - MARGIN;
                #pragma unroll
                for (int nt = 0; nt < 4; nt++) {
                    #pragma unroll
                    for (int i = 0; i < 4; i++) {
                        float v = acc[mt][nt][i];
                        int   r = (i < 2) ? r0 : r0 + 8;
                        float th = (i < 2) ? th0 : th1;
                        if (v >= th) {
                            int p = atomicAdd(&rowCnt[r], 1);
                            if (p < CAP)
                                cand[r * CAP + p] = (unsigned short)
                                    (n0 + warpN * 32 + nt * 8 + tc * 2 + (i & 1));
                        }
                        acc[mt][nt][i] = 0.0f;
                    }
                }
            }
        }
    }
    __syncthreads();

    // ---- Refinement + output writes: warp w owns rows [w*16, w*16+16) ----
    const float4* c4n = reinterpret_cast<const float4*>(g_cnorm);
    const float4* ce4 = reinterpret_cast<const float4*>(cent);
    float* outHard = out + (size_t)NB * ND;
    float* outOH   = outHard + NB;

    for (int rr = 0; rr < 16; rr++) {
        int r = wid * 16 + rr;
        int b = m0 + r;
        int cnt = rowCnt[r];
        int winner;
        if (cnt == 1) {
            winner = cand[r * CAP];
        } else {
            // exact fp32 dots; q row cached in registers
            float4 aq[4];
            const float4* qr = q4 + (size_t)b * 128;
            #pragma unroll
            for (int i = 0; i < 4; i++) aq[i] = qr[lane + 32 * i];
            float bv = -3.4e38f; int bi = NP;
            int lim = (cnt <= CAP) ? cnt : NP;   // overflow -> full exact scan
            for (int j = 0; j < lim; j++) {
                int col = (cnt <= CAP) ? (int)cand[r * CAP + j] : j;
                const float4* cr = c4n + (size_t)col * 128;
                float s = 0.0f;
                #pragma unroll
                for (int i = 0; i < 4; i++) {
                    float4 cc = cr[lane + 32 * i];
                    s = fmaf(aq[i].x, cc.x, fmaf(aq[i].y, cc.y,
                        fmaf(aq[i].z, cc.z, fmaf(aq[i].w, cc.w, s))));
                }
                #pragma unroll
                for (int o = 16; o > 0; o >>= 1)
                    s += __shfl_xor_sync(FULL, s, o);
                if (s > bv || (s == bv && col < bi)) { bv = s; bi = col; }
            }
            winner = bi;
        }

        // context gather (raw centroids)
        float4* ctx = reinterpret_cast<float4*>(out + (size_t)b * ND);
        #pragma unroll
        for (int i = 0; i < 4; i++)
            ctx[lane + 32 * i] = ce4[(size_t)winner * 128 + lane + 32 * i];
        if (lane == 0) outHard[b] = (float)winner;
        // full one-hot row (zeros + 1.0)
        float4* oh = reinterpret_cast<float4*>(outOH + (size_t)b * NP);
        int wq = winner >> 2, wr = winner & 3;
        #pragma unroll
        for (int i = 0; i < 8; i++) {
            int j = lane + 32 * i;
            float4 z = make_float4(0.f, 0.f, 0.f, 0.f);
            if (j == wq) reinterpret_cast<float*>(&z)[wr] = 1.0f;
            oh[j] = z;
        }
    }
}

// ---------------------------------------------------------------------------
// Launch: out = [context (B*D) | hard (B) | routing (B*P)] as float32
// ---------------------------------------------------------------------------
extern "C" void kernel_launch(void* const* d_in, const int* in_sizes, int n_in,
                              void* d_out, int out_size) {
    const float* q    = (const float*)d_in[0];  // (B, D) fp32
    const float* cent = (const float*)d_in[1];  // (P, D) fp32
    float* out = (float*)d_out;

    cudaFuncSetAttribute(fused_kernel,
                         cudaFuncAttributeMaxDynamicSharedMemorySize, SMEM_TOTAL);
    normalize_centroids<<<NP, 128>>>(cent);
    fused_kernel<<<NB / 128, 256, SMEM_TOTAL>>>(q, cent, out);
}

// round 6
// speedup vs baseline: 1.1960x; 1.1960x over previous
#include <cuda_runtime.h>
#include <cuda_bf16.h>
#include <cstdint>

#define NB 65536   // batch
#define ND 512     // embed dim
#define NP 1024    // prototypes
#define MARGIN 0.08f
#define CAP 16

// Device-global scratch (no runtime allocation allowed)
static __device__ float          g_cnorm[NP * ND];      // normalized centroids fp32
static __device__ __nv_bfloat16  g_cnorm_bf[NP * ND];   // normalized centroids bf16

// Order-preserving float<->uint mapping (for atomicMax on floats)
__device__ __forceinline__ unsigned fmap(float f) {
    unsigned u = __float_as_uint(f);
    return (u & 0x80000000u) ? ~u : (u | 0x80000000u);
}
__device__ __forceinline__ float funmap(unsigned u) {
    u = (u & 0x80000000u) ? (u & 0x7fffffffu) : ~u;
    return __uint_as_float(u);
}

__device__ __forceinline__ uint32_t smem_u32(const void* p) {
    uint32_t a;
    asm("{ .reg .u64 t; cvta.to.shared.u64 t, %1; cvt.u32.u64 %0, t; }"
        : "=r"(a) : "l"(p));
    return a;
}

__device__ __forceinline__ void ldsm_x4(unsigned& r0, unsigned& r1,
                                        unsigned& r2, unsigned& r3, uint32_t addr) {
    asm volatile("ldmatrix.sync.aligned.m8n8.x4.shared.b16 {%0,%1,%2,%3}, [%4];"
                 : "=r"(r0), "=r"(r1), "=r"(r2), "=r"(r3) : "r"(addr));
}

__device__ __forceinline__ void mma16816(float* c, const unsigned* a, const unsigned* b) {
    asm volatile(
        "mma.sync.aligned.m16n8k16.row.col.f32.bf16.bf16.f32 "
        "{%0,%1,%2,%3},{%4,%5,%6,%7},{%8,%9},{%0,%1,%2,%3};\n"
        : "+f"(c[0]), "+f"(c[1]), "+f"(c[2]), "+f"(c[3])
        : "r"(a[0]), "r"(a[1]), "r"(a[2]), "r"(a[3]), "r"(b[0]), "r"(b[1]));
}

// ---------------------------------------------------------------------------
// Kernel 1: L2-normalize centroids -> fp32 + bf16 copies.
// ---------------------------------------------------------------------------
__global__ void normalize_centroids(const float* __restrict__ cent) {
    int row = blockIdx.x;
    int t   = threadIdx.x;  // 0..127
    float4 v = reinterpret_cast<const float4*>(cent + (size_t)row * ND)[t];
    float ss = v.x * v.x + v.y * v.y + v.z * v.z + v.w * v.w;
    #pragma unroll
    for (int o = 16; o > 0; o >>= 1) ss += __shfl_down_sync(0xffffffffu, ss, o);
    __shared__ float sred[4];
    if ((t & 31) == 0) sred[t >> 5] = ss;
    __syncthreads();
    float tot   = sred[0] + sred[1] + sred[2] + sred[3];
    float scale = 1.0f / fmaxf(sqrtf(tot), 1e-12f);
    float4 o4 = make_float4(v.x * scale, v.y * scale, v.z * scale, v.w * scale);
    reinterpret_cast<float4*>(g_cnorm + (size_t)row * ND)[t] = o4;
    __nv_bfloat162 p0 = __floats2bfloat162_rn(o4.x, o4.y);
    __nv_bfloat162 p1 = __floats2bfloat162_rn(o4.z, o4.w);
    uint2 pk = make_uint2(*reinterpret_cast<unsigned*>(&p0),
                          *reinterpret_cast<unsigned*>(&p1));
    reinterpret_cast<uint2*>(g_cnorm_bf)[(size_t)row * (ND / 4) + t] = pk;
}

// ---------------------------------------------------------------------------
// Kernel 2: fused GEMM-argmax. 512 threads (16 warps), CTA owns 128 rows.
//  - warp grid 4M x 4N, warp tile 32x32 (2 m-subtiles x 4 n-subtiles)
//  - A resident in smem bf16 (128 x 512, stride 520)
//  - B streamed via cp.async.cg, 4-deep ring of 128x64 chunks (stride 72)
//  - ldmatrix fragment loads, mma.sync bf16 HMMA
//  - per-n-tile running max + margin candidates, exact fp32 refinement,
//    fused output writes (context gather, hard index, full one-hot)
// ---------------------------------------------------------------------------
#define ASTR 520        // bf16 elems per A row (512 + 8 pad -> 1040B)
#define BSTR 72         // bf16 elems per B row (64 + 8 pad -> 144B)
#define OFF_STATM 0                      // rowMaxU: 128 u32
#define OFF_CNT   512                    // rowCnt:  128 int
#define OFF_CAND  1024                   // cand:    128*CAP ushort (4096B)
#define OFF_A     5120
#define OFF_B     (OFF_A + 128 * ASTR * 2)   // 138240
#define BUFB      (128 * BSTR * 2)           // 18432
#define SMEM_TOTAL (OFF_B + 4 * BUFB)        // 211968

__global__ __launch_bounds__(512, 1) void fused_kernel(
    const float* __restrict__ q, const float* __restrict__ cent,
    float* __restrict__ out) {
    extern __shared__ char sm[];
    uint32_t sb = smem_u32(sm);
    unsigned*       rowMaxU = reinterpret_cast<unsigned*>(sm + OFF_STATM);
    int*            rowCnt  = reinterpret_cast<int*>(sm + OFF_CNT);
    unsigned short* cand    = reinterpret_cast<unsigned short*>(sm + OFF_CAND);
    __nv_bfloat16*  sA      = reinterpret_cast<__nv_bfloat16*>(sm + OFF_A);

    const unsigned FULL = 0xffffffffu;
    int tid  = threadIdx.x;
    int lane = tid & 31, wid = tid >> 5;
    int warpM = wid & 3, warpN = wid >> 2;   // 4 x 4 warp grid, warp tile 32x32
    int g = lane >> 2, tc = lane & 3;
    int m0 = blockIdx.x * 128;

    if (tid < 128) { rowMaxU[tid] = 0u; rowCnt[tid] = 0; }

    // ---- Load resident A tile: 128 x 512 fp32 -> bf16 ----
    const float4* q4 = reinterpret_cast<const float4*>(q);
    #pragma unroll 4
    for (int e = tid; e < 128 * 128; e += 512) {
        int row = e >> 7, c = e & 127;
        float4 v = q4[(size_t)(m0 + row) * 128 + c];
        __nv_bfloat162 p0 = __floats2bfloat162_rn(v.x, v.y);
        __nv_bfloat162 p1 = __floats2bfloat162_rn(v.z, v.w);
        uint2 pk = make_uint2(*reinterpret_cast<unsigned*>(&p0),
                              *reinterpret_cast<unsigned*>(&p1));
        *reinterpret_cast<uint2*>(&sA[row * ASTR + c * 4]) = pk;
    }

    float acc[2][4][4];
    #pragma unroll
    for (int mt = 0; mt < 2; mt++)
        #pragma unroll
        for (int nt = 0; nt < 4; nt++)
            #pragma unroll
            for (int i = 0; i < 4; i++) acc[mt][nt][i] = 0.0f;

    // B streaming: chunk c = (n-tile c>>3) x (k-chunk c&7), 128 rows x 64 k.
    // 16KB per chunk; each of 512 threads loads 32B via 2x cp.async 16B.
    int brow_ld = tid >> 2, bq = tid & 3;
    uint32_t dst_base = sb + OFF_B + brow_ld * 144 + bq * 32;
    const char* src_base = reinterpret_cast<const char*>(g_cnorm_bf) +
                           (size_t)brow_ld * 1024 + bq * 32;
    auto issue_chunk = [&](int c) {
        uint32_t dst = dst_base + (c & 3) * BUFB;
        const char* src = src_base + (size_t)(c >> 3) * 131072 + (c & 7) * 128;
        #pragma unroll
        for (int i = 0; i < 2; i++)
            asm volatile("cp.async.cg.shared.global [%0], [%1], 16;"
                         :: "r"(dst + i * 16), "l"(src + i * 16));
        asm volatile("cp.async.commit_group;" ::: "memory");
    };
    issue_chunk(0); issue_chunk(1); issue_chunk(2);

    // ldmatrix per-lane addresses
    uint32_t aAddr = sb + OFF_A +
        ((warpM * 32 + (lane & 15)) * ASTR + ((lane >> 4) << 3)) * 2;
    uint32_t bOff =
        ((warpN * 32 + (lane & 7) + ((lane >> 4) << 3)) * BSTR +
         (((lane >> 3) & 1) << 3)) * 2;

    // ---- Main loop: 64 chunks = 8 n-tiles x 8 k-steps of 64 ----
    for (int c = 0; c < 64; c++) {
        if (c <= 61)      asm volatile("cp.async.wait_group 2;" ::: "memory");
        else if (c == 62) asm volatile("cp.async.wait_group 1;" ::: "memory");
        else              asm volatile("cp.async.wait_group 0;" ::: "memory");
        __syncthreads();
        if (c + 3 < 64) issue_chunk(c + 3);

        uint32_t bufbase = sb + OFF_B + (c & 3) * BUFB + bOff;
        int kbase = (c & 7) * 64;

        #pragma unroll
        for (int kk = 0; kk < 64; kk += 16) {
            unsigned a[2][4], b[4][2];
            #pragma unroll
            for (int mt = 0; mt < 2; mt++)
                ldsm_x4(a[mt][0], a[mt][1], a[mt][2], a[mt][3],
                        aAddr + (mt * 16 * ASTR + kbase + kk) * 2);
            #pragma unroll
            for (int p = 0; p < 2; p++) {
                unsigned r0, r1, r2, r3;
                ldsm_x4(r0, r1, r2, r3, bufbase + (p * 16 * BSTR + kk) * 2);
                b[2 * p][0] = r0; b[2 * p][1] = r1;
                b[2 * p + 1][0] = r2; b[2 * p + 1][1] = r3;
            }
            #pragma unroll
            for (int mt = 0; mt < 2; mt++)
                #pragma unroll
                for (int nt = 0; nt < 4; nt++)
                    mma16816(acc[mt][nt], a[mt], b[nt]);
        }

        if ((c & 7) == 7) {   // n-tile finished: argmax epilogue
            int n0 = (c >> 3) * 128;
            #pragma unroll
            for (int mt = 0; mt < 2; mt++) {
                float v0 = -3.4e38f, v1 = -3.4e38f;
                #pragma unroll
                for (int nt = 0; nt < 4; nt++) {
                    v0 = fmaxf(v0, fmaxf(acc[mt][nt][0], acc[mt][nt][1]));
                    v1 = fmaxf(v1, fmaxf(acc[mt][nt][2], acc[mt][nt][3]));
                }
                v0 = fmaxf(v0, __shfl_xor_sync(FULL, v0, 1));
                v0 = fmaxf(v0, __shfl_xor_sync(FULL, v0, 2));
                v1 = fmaxf(v1, __shfl_xor_sync(FULL, v1, 1));
                v1 = fmaxf(v1, __shfl_xor_sync(FULL, v1, 2));
                if (tc == 0) {
                    int r = warpM * 32 + mt * 16 + g;
                    atomicMax(&rowMaxU[r], fmap(v0));
                    atomicMax(&rowMaxU[r + 8], fmap(v1));
                }
            }
            __syncthreads();
            #pragma unroll
            for (int mt = 0; mt < 2; mt++) {
                int r0 = warpM * 32 + mt * 16 + g;
                float th0 = funmap(rowMaxU[r0]) - MARGIN;
                float th1 = funmap(rowMaxU[r0 + 8]) - MARGIN;
                #pragma unroll
                for (int nt = 0; nt < 4; nt++) {
                    #pragma unroll
                    for (int i = 0; i < 4; i++) {
                        float v = acc[mt][nt][i];
                        int   r = (i < 2) ? r0 : r0 + 8;
                        float th = (i < 2) ? th0 : th1;
                        if (v >= th) {
                            int p = atomicAdd(&rowCnt[r], 1);
                            if (p < CAP)
                                cand[r * CAP + p] = (unsigned short)
                                    (n0 + warpN * 32 + nt * 8 + tc * 2 + (i & 1));
                        }
                        acc[mt][nt][i] = 0.0f;
                    }
                }
            }
        }
    }
    __syncthreads();

    // ---- Refinement + output writes: warp w owns rows [w*8, w*8+8) ----
    const float4* c4n = reinterpret_cast<const float4*>(g_cnorm);
    const float4* ce4 = reinterpret_cast<const float4*>(cent);
    float* outHard = out + (size_t)NB * ND;
    float* outOH   = outHard + NB;

    for (int rr = 0; rr < 8; rr++) {
        int r = wid * 8 + rr;
        int b = m0 + r;
        int cnt = rowCnt[r];
        int winner;
        if (cnt == 1) {
            winner = cand[r * CAP];
        } else {
            // exact fp32 dots; q row cached in registers
            float4 aq[4];
            const float4* qr = q4 + (size_t)b * 128;
            #pragma unroll
            for (int i = 0; i < 4; i++) aq[i] = qr[lane + 32 * i];
            float bv = -3.4e38f; int bi = NP;
            int lim = (cnt <= CAP) ? cnt : NP;   // overflow -> full exact scan
            for (int j = 0; j < lim; j++) {
                int col = (cnt <= CAP) ? (int)cand[r * CAP + j] : j;
                const float4* cr = c4n + (size_t)col * 128;
                float s = 0.0f;
                #pragma unroll
                for (int i = 0; i < 4; i++) {
                    float4 cc = cr[lane + 32 * i];
                    s = fmaf(aq[i].x, cc.x, fmaf(aq[i].y, cc.y,
                        fmaf(aq[i].z, cc.z, fmaf(aq[i].w, cc.w, s))));
                }
                #pragma unroll
                for (int o = 16; o > 0; o >>= 1)
                    s += __shfl_xor_sync(FULL, s, o);
                if (s > bv || (s == bv && col < bi)) { bv = s; bi = col; }
            }
            winner = bi;
        }

        // context gather (raw centroids)
        float4* ctx = reinterpret_cast<float4*>(out + (size_t)b * ND);
        #pragma unroll
        for (int i = 0; i < 4; i++)
            ctx[lane + 32 * i] = ce4[(size_t)winner * 128 + lane + 32 * i];
        if (lane == 0) outHard[b] = (float)winner;
        // full one-hot row (zeros + 1.0)
        float4* oh = reinterpret_cast<float4*>(outOH + (size_t)b * NP);
        int wq = winner >> 2, wr = winner & 3;
        #pragma unroll
        for (int i = 0; i < 8; i++) {
            int j = lane + 32 * i;
            float4 z = make_float4(0.f, 0.f, 0.f, 0.f);
            if (j == wq) reinterpret_cast<float*>(&z)[wr] = 1.0f;
            oh[j] = z;
        }
    }
}

// ---------------------------------------------------------------------------
// Launch: out = [context (B*D) | hard (B) | routing (B*P)] as float32
// ---------------------------------------------------------------------------
extern "C" void kernel_launch(void* const* d_in, const int* in_sizes, int n_in,
                              void* d_out, int out_size) {
    const float* q    = (const float*)d_in[0];  // (B, D) fp32
    const float* cent = (const float*)d_in[1];  // (P, D) fp32
    float* out = (float*)d_out;

    cudaFuncSetAttribute(fused_kernel,
                         cudaFuncAttributeMaxDynamicSharedMemorySize, SMEM_TOTAL);
    normalize_centroids<<<NP, 128>>>(cent);
    fused_kernel<<<NB / 128, 512, SMEM_TOTAL>>>(q, cent, out);
}

// round 7
// speedup vs baseline: 1.4265x; 1.1927x over previous
#include <cuda_runtime.h>
#include <cuda_bf16.h>
#include <cstdint>

#define NB 65536   // batch
#define ND 512     // embed dim
#define NP 1024    // prototypes
#define MARGIN 0.08f
#define CAP 16

// Device-global scratch (no runtime allocation allowed)
static __device__ float          g_cnorm[NP * ND];      // normalized centroids fp32
static __device__ __nv_bfloat16  g_cnorm_bf[NP * ND];   // normalized centroids bf16

// Order-preserving float<->uint mapping (for atomicMax on floats)
__device__ __forceinline__ unsigned fmap(float f) {
    unsigned u = __float_as_uint(f);
    return (u & 0x80000000u) ? ~u : (u | 0x80000000u);
}
__device__ __forceinline__ float funmap(unsigned u) {
    u = (u & 0x80000000u) ? (u & 0x7fffffffu) : ~u;
    return __uint_as_float(u);
}

__device__ __forceinline__ uint32_t smem_u32(const void* p) {
    uint32_t a;
    asm("{ .reg .u64 t; cvta.to.shared.u64 t, %1; cvt.u32.u64 %0, t; }"
        : "=r"(a) : "l"(p));
    return a;
}

__device__ __forceinline__ void ldsm_x4(unsigned& r0, unsigned& r1,
                                        unsigned& r2, unsigned& r3, uint32_t addr) {
    asm volatile("ldmatrix.sync.aligned.m8n8.x4.shared.b16 {%0,%1,%2,%3}, [%4];"
                 : "=r"(r0), "=r"(r1), "=r"(r2), "=r"(r3) : "r"(addr));
}

__device__ __forceinline__ void mma16816(float* c, const unsigned* a, const unsigned* b) {
    asm volatile(
        "mma.sync.aligned.m16n8k16.row.col.f32.bf16.bf16.f32 "
        "{%0,%1,%2,%3},{%4,%5,%6,%7},{%8,%9},{%0,%1,%2,%3};\n"
        : "+f"(c[0]), "+f"(c[1]), "+f"(c[2]), "+f"(c[3])
        : "r"(a[0]), "r"(a[1]), "r"(a[2]), "r"(a[3]), "r"(b[0]), "r"(b[1]));
}

// ---------------------------------------------------------------------------
// Kernel 1: L2-normalize centroids -> fp32 + bf16 copies.
// ---------------------------------------------------------------------------
__global__ void normalize_centroids(const float* __restrict__ cent) {
    int row = blockIdx.x;
    int t   = threadIdx.x;  // 0..127
    float4 v = reinterpret_cast<const float4*>(cent + (size_t)row * ND)[t];
    float ss = v.x * v.x + v.y * v.y + v.z * v.z + v.w * v.w;
    #pragma unroll
    for (int o = 16; o > 0; o >>= 1) ss += __shfl_down_sync(0xffffffffu, ss, o);
    __shared__ float sred[4];
    if ((t & 31) == 0) sred[t >> 5] = ss;
    __syncthreads();
    float tot   = sred[0] + sred[1] + sred[2] + sred[3];
    float scale = 1.0f / fmaxf(sqrtf(tot), 1e-12f);
    float4 o4 = make_float4(v.x * scale, v.y * scale, v.z * scale, v.w * scale);
    reinterpret_cast<float4*>(g_cnorm + (size_t)row * ND)[t] = o4;
    __nv_bfloat162 p0 = __floats2bfloat162_rn(o4.x, o4.y);
    __nv_bfloat162 p1 = __floats2bfloat162_rn(o4.z, o4.w);
    uint2 pk = make_uint2(*reinterpret_cast<unsigned*>(&p0),
                          *reinterpret_cast<unsigned*>(&p1));
    reinterpret_cast<uint2*>(g_cnorm_bf)[(size_t)row * (ND / 4) + t] = pk;
}

// ---------------------------------------------------------------------------
// Kernel 2: fused GEMM-argmax. 512 threads (16 warps), CTA owns 128 rows.
//  - warp grid 4M x 4N, warp tile 32x32
//  - A resident in smem bf16 (128 x 512, stride 520), loaded once
//  - 4 INDEPENDENT group pipelines (group = 4 warps sharing warpN):
//    each group streams its own 32-col B slices via cp.async into a private
//    4-slot ring, synced only by a named barrier (bar.sync gid+1, 128).
//    NO CTA-wide __syncthreads in the mainloop.
//  - argmax coordination is lock-free: shared atomicMax rowMax (monotone ->
//    stale reads only lower the threshold = candidate superset, still exact),
//    atomicAdd candidate lists; single __syncthreads before refinement.
// ---------------------------------------------------------------------------
#define ASTR 520        // bf16 elems per A row (512 + 8 pad)
#define BSTR 72         // bf16 elems per B slice row (64 + 8 pad -> 144B)
#define SLICE_B (32 * BSTR * 2)              // 4608 bytes per slice
#define OFF_STATM 0                          // rowMaxU: 128 u32
#define OFF_CNT   512                        // rowCnt:  128 int
#define OFF_CAND  1024                       // cand:    128*CAP ushort
#define OFF_A     5120
#define OFF_B     (OFF_A + 128 * ASTR * 2)   // 138240
#define SMEM_TOTAL (OFF_B + 4 * 4 * SLICE_B) // 211968

__global__ __launch_bounds__(512, 1) void fused_kernel(
    const float* __restrict__ q, const float* __restrict__ cent,
    float* __restrict__ out) {
    extern __shared__ char sm[];
    uint32_t sb = smem_u32(sm);
    unsigned*       rowMaxU = reinterpret_cast<unsigned*>(sm + OFF_STATM);
    int*            rowCnt  = reinterpret_cast<int*>(sm + OFF_CNT);
    unsigned short* cand    = reinterpret_cast<unsigned short*>(sm + OFF_CAND);
    __nv_bfloat16*  sA      = reinterpret_cast<__nv_bfloat16*>(sm + OFF_A);

    const unsigned FULL = 0xffffffffu;
    int tid  = threadIdx.x;
    int lane = tid & 31, wid = tid >> 5;
    int warpM = wid & 3, warpN = wid >> 2;   // 4 x 4 warp grid, warp tile 32x32
    int gid = warpN;                          // pipeline group id (0..3)
    int ltid = warpM * 32 + lane;             // thread id within group (0..127)
    int g = lane >> 2, tc = lane & 3;
    int m0 = blockIdx.x * 128;
    unsigned barid = gid + 1;

    if (tid < 128) { rowMaxU[tid] = 0u; rowCnt[tid] = 0; }

    // ---- Load resident A tile: 128 x 512 fp32 -> bf16 ----
    const float4* q4 = reinterpret_cast<const float4*>(q);
    #pragma unroll 4
    for (int e = tid; e < 128 * 128; e += 512) {
        int row = e >> 7, c = e & 127;
        float4 v = q4[(size_t)(m0 + row) * 128 + c];
        __nv_bfloat162 p0 = __floats2bfloat162_rn(v.x, v.y);
        __nv_bfloat162 p1 = __floats2bfloat162_rn(v.z, v.w);
        uint2 pk = make_uint2(*reinterpret_cast<unsigned*>(&p0),
                              *reinterpret_cast<unsigned*>(&p1));
        *reinterpret_cast<uint2*>(&sA[row * ASTR + c * 4]) = pk;
    }

    float acc[2][4][4];
    #pragma unroll
    for (int mt = 0; mt < 2; mt++)
        #pragma unroll
        for (int nt = 0; nt < 4; nt++)
            #pragma unroll
            for (int i = 0; i < 4; i++) acc[mt][nt][i] = 0.0f;

    // Group B pipeline: chunk c = (n-tile c>>3) x (k-chunk c&7).
    // Group's slice = 32 centroid rows [n0 + gid*32, +32) x 64 k = 4KB.
    // 128 group threads: each loads 32B (2 x 16B cp.async).
    int brow = ltid >> 2, bq = ltid & 3;
    uint32_t grp_base = sb + OFF_B + gid * (4 * SLICE_B);
    uint32_t dst_base = grp_base + brow * 144 + bq * 32;
    const char* src_base = reinterpret_cast<const char*>(g_cnorm_bf) +
                           (size_t)(gid * 32 + brow) * 1024 + bq * 32;
    auto issue_chunk = [&](int c) {
        uint32_t dst = dst_base + (c & 3) * SLICE_B;
        const char* src = src_base + (size_t)(c >> 3) * 131072 + (c & 7) * 128;
        asm volatile("cp.async.cg.shared.global [%0], [%1], 16;"
                     :: "r"(dst), "l"(src));
        asm volatile("cp.async.cg.shared.global [%0], [%1], 16;"
                     :: "r"(dst + 16), "l"(src + 16));
        asm volatile("cp.async.commit_group;" ::: "memory");
    };
    issue_chunk(0); issue_chunk(1); issue_chunk(2);

    // ldmatrix per-lane addresses
    uint32_t aAddr = sb + OFF_A +
        ((warpM * 32 + (lane & 15)) * ASTR + ((lane >> 4) << 3)) * 2;
    uint32_t bLoc =
        ((((lane & 7) + ((lane >> 4) << 3)) * BSTR) + (((lane >> 3) & 1) << 3)) * 2;

    __syncthreads();   // A visible, rowMax/cnt initialized

    // ---- Main loop: 64 chunks, group-local sync only ----
    for (int c = 0; c < 64; c++) {
        if (c <= 60)      asm volatile("cp.async.wait_group 2;" ::: "memory");
        else if (c == 61) asm volatile("cp.async.wait_group 2;" ::: "memory");
        else if (c == 62) asm volatile("cp.async.wait_group 1;" ::: "memory");
        else              asm volatile("cp.async.wait_group 0;" ::: "memory");
        asm volatile("bar.sync %0, %1;" :: "r"(barid), "r"(128) : "memory");
        if (c + 3 < 64) issue_chunk(c + 3);

        uint32_t bufbase = grp_base + (c & 3) * SLICE_B + bLoc;
        int kbase = (c & 7) * 64;

        #pragma unroll
        for (int kk = 0; kk < 64; kk += 16) {
            unsigned a[2][4], b[4][2];
            #pragma unroll
            for (int mt = 0; mt < 2; mt++)
                ldsm_x4(a[mt][0], a[mt][1], a[mt][2], a[mt][3],
                        aAddr + (mt * 16 * ASTR + kbase + kk) * 2);
            #pragma unroll
            for (int p = 0; p < 2; p++) {
                unsigned r0, r1, r2, r3;
                ldsm_x4(r0, r1, r2, r3, bufbase + (p * 16 * BSTR + kk) * 2);
                b[2 * p][0] = r0; b[2 * p][1] = r1;
                b[2 * p + 1][0] = r2; b[2 * p + 1][1] = r3;
            }
            #pragma unroll
            for (int mt = 0; mt < 2; mt++)
                #pragma unroll
                for (int nt = 0; nt < 4; nt++)
                    mma16816(acc[mt][nt], a[mt], b[nt]);
        }

        if ((c & 7) == 7) {   // n-tile finished: group-local argmax epilogue
            int n0 = (c >> 3) * 128;
            #pragma unroll
            for (int mt = 0; mt < 2; mt++) {
                float v0 = -3.4e38f, v1 = -3.4e38f;
                #pragma unroll
                for (int nt = 0; nt < 4; nt++) {
                    v0 = fmaxf(v0, fmaxf(acc[mt][nt][0], acc[mt][nt][1]));
                    v1 = fmaxf(v1, fmaxf(acc[mt][nt][2], acc[mt][nt][3]));
                }
                v0 = fmaxf(v0, __shfl_xor_sync(FULL, v0, 1));
                v0 = fmaxf(v0, __shfl_xor_sync(FULL, v0, 2));
                v1 = fmaxf(v1, __shfl_xor_sync(FULL, v1, 1));
                v1 = fmaxf(v1, __shfl_xor_sync(FULL, v1, 2));
                if (tc == 0) {
                    int r = warpM * 32 + mt * 16 + g;
                    atomicMax(&rowMaxU[r], fmap(v0));
                    atomicMax(&rowMaxU[r + 8], fmap(v1));
                }
            }
            // group barrier: own group's maxima published; other groups'
            // maxima arrive opportunistically (stale read -> lower threshold
            // -> candidate superset: still exact).
            asm volatile("bar.sync %0, %1;" :: "r"(barid), "r"(128) : "memory");
            #pragma unroll
            for (int mt = 0; mt < 2; mt++) {
                int r0 = warpM * 32 + mt * 16 + g;
                float th0 = funmap(rowMaxU[r0]) - MARGIN;
                float th1 = funmap(rowMaxU[r0 + 8]) - MARGIN;
                #pragma unroll
                for (int nt = 0; nt < 4; nt++) {
                    #pragma unroll
                    for (int i = 0; i < 4; i++) {
                        float v = acc[mt][nt][i];
                        int   r = (i < 2) ? r0 : r0 + 8;
                        float th = (i < 2) ? th0 : th1;
                        if (v >= th) {
                            int p = atomicAdd(&rowCnt[r], 1);
                            if (p < CAP)
                                cand[r * CAP + p] = (unsigned short)
                                    (n0 + warpN * 32 + nt * 8 + tc * 2 + (i & 1));
                        }
                        acc[mt][nt][i] = 0.0f;
                    }
                }
            }
        }
    }
    __syncthreads();   // all groups done: candidates complete

    // ---- Refinement + output writes: warp w owns rows [w*8, w*8+8) ----
    const float4* c4n = reinterpret_cast<const float4*>(g_cnorm);
    const float4* ce4 = reinterpret_cast<const float4*>(cent);
    float* outHard = out + (size_t)NB * ND;
    float* outOH   = outHard + NB;

    for (int rr = 0; rr < 8; rr++) {
        int r = wid * 8 + rr;
        int b = m0 + r;
        int cnt = rowCnt[r];
        int winner;
        if (cnt == 1) {
            winner = cand[r * CAP];
        } else {
            // exact fp32 dots; q row cached in registers
            float4 aq[4];
            const float4* qr = q4 + (size_t)b * 128;
            #pragma unroll
            for (int i = 0; i < 4; i++) aq[i] = qr[lane + 32 * i];
            float bv = -3.4e38f; int bi = NP;
            int lim = (cnt <= CAP) ? cnt : NP;   // overflow -> full exact scan
            for (int j = 0; j < lim; j++) {
                int col = (cnt <= CAP) ? (int)cand[r * CAP + j] : j;
                const float4* cr = c4n + (size_t)col * 128;
                float s = 0.0f;
                #pragma unroll
                for (int i = 0; i < 4; i++) {
                    float4 cc = cr[lane + 32 * i];
                    s = fmaf(aq[i].x, cc.x, fmaf(aq[i].y, cc.y,
                        fmaf(aq[i].z, cc.z, fmaf(aq[i].w, cc.w, s))));
                }
                #pragma unroll
                for (int o = 16; o > 0; o >>= 1)
                    s += __shfl_xor_sync(FULL, s, o);
                if (s > bv || (s == bv && col < bi)) { bv = s; bi = col; }
            }
            winner = bi;
        }

        // context gather (raw centroids)
        float4* ctx = reinterpret_cast<float4*>(out + (size_t)b * ND);
        #pragma unroll
        for (int i = 0; i < 4; i++)
            ctx[lane + 32 * i] = ce4[(size_t)winner * 128 + lane + 32 * i];
        if (lane == 0) outHard[b] = (float)winner;
        // full one-hot row (zeros + 1.0)
        float4* oh = reinterpret_cast<float4*>(outOH + (size_t)b * NP);
        int wq = winner >> 2, wr = winner & 3;
        #pragma unroll
        for (int i = 0; i < 8; i++) {
            int j = lane + 32 * i;
            float4 z = make_float4(0.f, 0.f, 0.f, 0.f);
            if (j == wq) reinterpret_cast<float*>(&z)[wr] = 1.0f;
            oh[j] = z;
        }
    }
}

// ---------------------------------------------------------------------------
// Launch: out = [context (B*D) | hard (B) | routing (B*P)] as float32
// ---------------------------------------------------------------------------
extern "C" void kernel_launch(void* const* d_in, const int* in_sizes, int n_in,
                              void* d_out, int out_size) {
    const float* q    = (const float*)d_in[0];  // (B, D) fp32
    const float* cent = (const float*)d_in[1];  // (P, D) fp32
    float* out = (float*)d_out;

    cudaFuncSetAttribute(fused_kernel,
                         cudaFuncAttributeMaxDynamicSharedMemorySize, SMEM_TOTAL);
    normalize_centroids<<<NP, 128>>>(cent);
    fused_kernel<<<NB / 128, 512, SMEM_TOTAL>>>(q, cent, out);
}

// round 8
// speedup vs baseline: 1.4315x; 1.0035x over previous
#include <cuda_runtime.h>
#include <cuda_bf16.h>
#include <cstdint>

#define NB 65536   // batch
#define ND 512     // embed dim
#define NP 1024    // prototypes
#define MARGIN 0.08f
#define CAP 16

// Device-global scratch (no runtime allocation allowed)
static __device__ float          g_cnorm[NP * ND];      // normalized centroids fp32
static __device__ __nv_bfloat16  g_cnorm_bf[NP * ND];   // normalized centroids bf16

// Order-preserving float<->uint mapping (for atomicMax on floats)
__device__ __forceinline__ unsigned fmap(float f) {
    unsigned u = __float_as_uint(f);
    return (u & 0x80000000u) ? ~u : (u | 0x80000000u);
}
__device__ __forceinline__ float funmap(unsigned u) {
    u = (u & 0x80000000u) ? (u & 0x7fffffffu) : ~u;
    return __uint_as_float(u);
}

__device__ __forceinline__ uint32_t smem_u32(const void* p) {
    uint32_t a;
    asm("{ .reg .u64 t; cvta.to.shared.u64 t, %1; cvt.u32.u64 %0, t; }"
        : "=r"(a) : "l"(p));
    return a;
}

__device__ __forceinline__ void ldsm_x4(unsigned& r0, unsigned& r1,
                                        unsigned& r2, unsigned& r3, uint32_t addr) {
    asm volatile("ldmatrix.sync.aligned.m8n8.x4.shared.b16 {%0,%1,%2,%3}, [%4];"
                 : "=r"(r0), "=r"(r1), "=r"(r2), "=r"(r3) : "r"(addr));
}

__device__ __forceinline__ void mma16816(float* c, const unsigned* a, const unsigned* b) {
    asm volatile(
        "mma.sync.aligned.m16n8k16.row.col.f32.bf16.bf16.f32 "
        "{%0,%1,%2,%3},{%4,%5,%6,%7},{%8,%9},{%0,%1,%2,%3};\n"
        : "+f"(c[0]), "+f"(c[1]), "+f"(c[2]), "+f"(c[3])
        : "r"(a[0]), "r"(a[1]), "r"(a[2]), "r"(a[3]), "r"(b[0]), "r"(b[1]));
}

// ---------------------------------------------------------------------------
// Kernel 1: L2-normalize centroids -> fp32 + bf16 copies.
// ---------------------------------------------------------------------------
__global__ void normalize_centroids(const float* __restrict__ cent) {
    int row = blockIdx.x;
    int t   = threadIdx.x;  // 0..127
    float4 v = reinterpret_cast<const float4*>(cent + (size_t)row * ND)[t];
    float ss = v.x * v.x + v.y * v.y + v.z * v.z + v.w * v.w;
    #pragma unroll
    for (int o = 16; o > 0; o >>= 1) ss += __shfl_down_sync(0xffffffffu, ss, o);
    __shared__ float sred[4];
    if ((t & 31) == 0) sred[t >> 5] = ss;
    __syncthreads();
    float tot   = sred[0] + sred[1] + sred[2] + sred[3];
    float scale = 1.0f / fmaxf(sqrtf(tot), 1e-12f);
    float4 o4 = make_float4(v.x * scale, v.y * scale, v.z * scale, v.w * scale);
    reinterpret_cast<float4*>(g_cnorm + (size_t)row * ND)[t] = o4;
    __nv_bfloat162 p0 = __floats2bfloat162_rn(o4.x, o4.y);
    __nv_bfloat162 p1 = __floats2bfloat162_rn(o4.z, o4.w);
    uint2 pk = make_uint2(*reinterpret_cast<unsigned*>(&p0),
                          *reinterpret_cast<unsigned*>(&p1));
    reinterpret_cast<uint2*>(g_cnorm_bf)[(size_t)row * (ND / 4) + t] = pk;
}

// ---------------------------------------------------------------------------
// Kernel 2: fused GEMM-argmax. 512 threads (16 warps), CTA owns 128 rows.
//  - 4 groups (group = 4 warps), group warp tile 32x64: group covers
//    128M x 64N; n-tile = 256 cols (4 groups), 4 n-tiles total.
//  - A resident in smem bf16 (128 x 512, stride 520), loaded once
//  - per-group B pipeline: 2-slot ring of 64-row x 64-K slices (cp.async),
//    issue-after-barrier schedule, group-local named barrier only.
//  - lock-free argmax coordination (atomicMax rowMax = monotone ->
//    stale read gives candidate superset, still exact), atomicAdd cands.
//  - exact fp32 refinement + fused output writes.
// ---------------------------------------------------------------------------
#define ASTR 520        // bf16 elems per A row (512 + 8 pad)
#define BSTR 72         // bf16 elems per B slice row (64 + 8 pad -> 144B)
#define SLICE_B (64 * BSTR * 2)              // 9216 bytes per slice (64 rows)
#define OFF_STATM 0                          // rowMaxU: 128 u32
#define OFF_CNT   512                        // rowCnt:  128 int
#define OFF_CAND  1024                       // cand:    128*CAP ushort
#define OFF_A     5120
#define OFF_B     (OFF_A + 128 * ASTR * 2)   // 138240
#define SMEM_TOTAL (OFF_B + 4 * 2 * SLICE_B) // 211968

__global__ __launch_bounds__(512, 1) void fused_kernel(
    const float* __restrict__ q, const float* __restrict__ cent,
    float* __restrict__ out) {
    extern __shared__ char sm[];
    uint32_t sb = smem_u32(sm);
    unsigned*       rowMaxU = reinterpret_cast<unsigned*>(sm + OFF_STATM);
    int*            rowCnt  = reinterpret_cast<int*>(sm + OFF_CNT);
    unsigned short* cand    = reinterpret_cast<unsigned short*>(sm + OFF_CAND);
    __nv_bfloat16*  sA      = reinterpret_cast<__nv_bfloat16*>(sm + OFF_A);

    const unsigned FULL = 0xffffffffu;
    int tid  = threadIdx.x;
    int lane = tid & 31, wid = tid >> 5;
    int warpM = wid & 3, gid = wid >> 2;     // group gid: 4 warps, tile 32x64
    int ltid = warpM * 32 + lane;            // thread id within group (0..127)
    int g = lane >> 2, tc = lane & 3;
    int m0 = blockIdx.x * 128;
    unsigned barid = gid + 1;

    if (tid < 128) { rowMaxU[tid] = 0u; rowCnt[tid] = 0; }

    // ---- Load resident A tile: 128 x 512 fp32 -> bf16 ----
    const float4* q4 = reinterpret_cast<const float4*>(q);
    #pragma unroll 4
    for (int e = tid; e < 128 * 128; e += 512) {
        int row = e >> 7, c = e & 127;
        float4 v = q4[(size_t)(m0 + row) * 128 + c];
        __nv_bfloat162 p0 = __floats2bfloat162_rn(v.x, v.y);
        __nv_bfloat162 p1 = __floats2bfloat162_rn(v.z, v.w);
        uint2 pk = make_uint2(*reinterpret_cast<unsigned*>(&p0),
                              *reinterpret_cast<unsigned*>(&p1));
        *reinterpret_cast<uint2*>(&sA[row * ASTR + c * 4]) = pk;
    }

    float acc[2][8][4];
    #pragma unroll
    for (int mt = 0; mt < 2; mt++)
        #pragma unroll
        for (int nt = 0; nt < 8; nt++)
            #pragma unroll
            for (int i = 0; i < 4; i++) acc[mt][nt][i] = 0.0f;

    // Group B pipeline: chunk c = (n-tile c>>3) x (k-chunk c&7).
    // Group slice = 64 centroid rows [nt*256 + gid*64, +64) x 64 K = 8KB.
    // 128 group threads: each loads 64B (4 x 16B cp.async).
    int brow = ltid >> 1, bq = ltid & 1;
    uint32_t grp_base = sb + OFF_B + gid * (2 * SLICE_B);
    uint32_t dst_base = grp_base + brow * 144 + bq * 64;
    const char* src_base = reinterpret_cast<const char*>(g_cnorm_bf) +
                           (size_t)(gid * 64 + brow) * 1024 + bq * 64;
    auto issue_chunk = [&](int c) {
        uint32_t dst = dst_base + (c & 1) * SLICE_B;
        const char* src = src_base + (size_t)(c >> 3) * 262144 + (c & 7) * 128;
        #pragma unroll
        for (int i = 0; i < 4; i++)
            asm volatile("cp.async.cg.shared.global [%0], [%1], 16;"
                         :: "r"(dst + i * 16), "l"(src + i * 16));
        asm volatile("cp.async.commit_group;" ::: "memory");
    };
    issue_chunk(0);

    // ldmatrix per-lane addresses
    uint32_t aAddr = sb + OFF_A +
        ((warpM * 32 + (lane & 15)) * ASTR + ((lane >> 4) << 3)) * 2;
    uint32_t bLoc =
        ((((lane & 7) + ((lane >> 4) << 3)) * BSTR) + (((lane >> 3) & 1) << 3)) * 2;

    __syncthreads();   // A visible, rowMax/cnt initialized

    // ---- Main loop: 32 chunks = 4 n-tiles x 8 k-chunks of 64 ----
    for (int c = 0; c < 32; c++) {
        asm volatile("cp.async.wait_group 0;" ::: "memory");
        asm volatile("bar.sync %0, %1;" :: "r"(barid), "r"(128) : "memory");
        if (c + 1 < 32) issue_chunk(c + 1);

        uint32_t bufbase = grp_base + (c & 1) * SLICE_B + bLoc;
        int kbase = (c & 7) * 64;

        #pragma unroll
        for (int kk = 0; kk < 64; kk += 16) {
            unsigned a[2][4], b[8][2];
            #pragma unroll
            for (int mt = 0; mt < 2; mt++)
                ldsm_x4(a[mt][0], a[mt][1], a[mt][2], a[mt][3],
                        aAddr + (mt * 16 * ASTR + kbase + kk) * 2);
            #pragma unroll
            for (int p = 0; p < 4; p++) {
                unsigned r0, r1, r2, r3;
                ldsm_x4(r0, r1, r2, r3,
                        bufbase + (p * 16 * BSTR + kk) * 2);
                b[2 * p][0] = r0; b[2 * p][1] = r1;
                b[2 * p + 1][0] = r2; b[2 * p + 1][1] = r3;
            }
            #pragma unroll
            for (int mt = 0; mt < 2; mt++)
                #pragma unroll
                for (int nt = 0; nt < 8; nt++)
                    mma16816(acc[mt][nt], a[mt], b[nt]);
        }

        if ((c & 7) == 7) {   // n-tile finished: group-local argmax epilogue
            int n0 = (c >> 3) * 256 + gid * 64;
            #pragma unroll
            for (int mt = 0; mt < 2; mt++) {
                float v0 = -3.4e38f, v1 = -3.4e38f;
                #pragma unroll
                for (int nt = 0; nt < 8; nt++) {
                    v0 = fmaxf(v0, fmaxf(acc[mt][nt][0], acc[mt][nt][1]));
                    v1 = fmaxf(v1, fmaxf(acc[mt][nt][2], acc[mt][nt][3]));
                }
                v0 = fmaxf(v0, __shfl_xor_sync(FULL, v0, 1));
                v0 = fmaxf(v0, __shfl_xor_sync(FULL, v0, 2));
                v1 = fmaxf(v1, __shfl_xor_sync(FULL, v1, 1));
                v1 = fmaxf(v1, __shfl_xor_sync(FULL, v1, 2));
                if (tc == 0) {
                    int r = warpM * 32 + mt * 16 + g;
                    atomicMax(&rowMaxU[r], fmap(v0));
                    atomicMax(&rowMaxU[r + 8], fmap(v1));
                }
            }
            // group barrier: own group's maxima published; other groups'
            // maxima arrive opportunistically (stale read -> lower threshold
            // -> candidate superset: still exact).
            asm volatile("bar.sync %0, %1;" :: "r"(barid), "r"(128) : "memory");
            #pragma unroll
            for (int mt = 0; mt < 2; mt++) {
                int r0 = warpM * 32 + mt * 16 + g;
                float th0 = funmap(rowMaxU[r0]) - MARGIN;
                float th1 = funmap(rowMaxU[r0 + 8]) - MARGIN;
                #pragma unroll
                for (int nt = 0; nt < 8; nt++) {
                    #pragma unroll
                    for (int i = 0; i < 4; i++) {
                        float v = acc[mt][nt][i];
                        int   r = (i < 2) ? r0 : r0 + 8;
                        float th = (i < 2) ? th0 : th1;
                        if (v >= th) {
                            int p = atomicAdd(&rowCnt[r], 1);
                            if (p < CAP)
                                cand[r * CAP + p] = (unsigned short)
                                    (n0 + nt * 8 + tc * 2 + (i & 1));
                        }
                        acc[mt][nt][i] = 0.0f;
                    }
                }
            }
        }
    }
    __syncthreads();   // all groups done: candidates complete

    // ---- Refinement + output writes: warp w owns rows [w*8, w*8+8) ----
    const float4* c4n = reinterpret_cast<const float4*>(g_cnorm);
    const float4* ce4 = reinterpret_cast<const float4*>(cent);
    float* outHard = out + (size_t)NB * ND;
    float* outOH   = outHard + NB;

    for (int rr = 0; rr < 8; rr++) {
        int r = wid * 8 + rr;
        int b = m0 + r;
        int cnt = rowCnt[r];
        int winner;
        if (cnt == 1) {
            winner = cand[r * CAP];
        } else {
            // exact fp32 dots; q row cached in registers
            float4 aq[4];
            const float4* qr = q4 + (size_t)b * 128;
            #pragma unroll
            for (int i = 0; i < 4; i++) aq[i] = qr[lane + 32 * i];
            float bv = -3.4e38f; int bi = NP;
            int lim = (cnt <= CAP) ? cnt : NP;   // overflow -> full exact scan
            for (int j = 0; j < lim; j++) {
                int col = (cnt <= CAP) ? (int)cand[r * CAP + j] : j;
                const float4* cr = c4n + (size_t)col * 128;
                float s = 0.0f;
                #pragma unroll
                for (int i = 0; i < 4; i++) {
                    float4 cc = cr[lane + 32 * i];
                    s = fmaf(aq[i].x, cc.x, fmaf(aq[i].y, cc.y,
                        fmaf(aq[i].z, cc.z, fmaf(aq[i].w, cc.w, s))));
                }
                #pragma unroll
                for (int o = 16; o > 0; o >>= 1)
                    s += __shfl_xor_sync(FULL, s, o);
                if (s > bv || (s == bv && col < bi)) { bv = s; bi = col; }
            }
            winner = bi;
        }

        // context gather (raw centroids)
        float4* ctx = reinterpret_cast<float4*>(out + (size_t)b * ND);
        #pragma unroll
        for (int i = 0; i < 4; i++)
            ctx[lane + 32 * i] = ce4[(size_t)winner * 128 + lane + 32 * i];
        if (lane == 0) outHard[b] = (float)winner;
        // full one-hot row (zeros + 1.0)
        float4* oh = reinterpret_cast<float4*>(outOH + (size_t)b * NP);
        int wq = winner >> 2, wr = winner & 3;
        #pragma unroll
        for (int i = 0; i < 8; i++) {
            int j = lane + 32 * i;
            float4 z = make_float4(0.f, 0.f, 0.f, 0.f);
            if (j == wq) reinterpret_cast<float*>(&z)[wr] = 1.0f;
            oh[j] = z;
        }
    }
}

// ---------------------------------------------------------------------------
// Launch: out = [context (B*D) | hard (B) | routing (B*P)] as float32
// ---------------------------------------------------------------------------
extern "C" void kernel_launch(void* const* d_in, const int* in_sizes, int n_in,
                              void* d_out, int out_size) {
    const float* q    = (const float*)d_in[0];  // (B, D) fp32
    const float* cent = (const float*)d_in[1];  // (P, D) fp32
    float* out = (float*)d_out;

    cudaFuncSetAttribute(fused_kernel,
                         cudaFuncAttributeMaxDynamicSharedMemorySize, SMEM_TOTAL);
    normalize_centroids<<<NP, 128>>>(cent);
    fused_kernel<<<NB / 128, 512, SMEM_TOTAL>>>(q, cent, out);
}